// round 3
// baseline (speedup 1.0000x reference)
#include <cuda_runtime.h>
#include <cstdint>

// Problem constants
#define B_      512
#define L_      512
#define KOBS    103
#define H_      512
#define G4      2048          // 4*H
#define KTOT    617           // 103 obs + 2 pos + 512 h
#define KP      620           // padded to multiple of 4
#define KPAD    640           // packed weight row stride (floats)
#define MB      32            // batch rows per cluster (group)
#define NPAIR   16            // MB/2 row-pairs
#define KROW    624           // inpP row stride in float2 (16B-aligned rows)
#define NTHREADS 256
#define NCTAS   128           // 16 clusters x 8 CTAs
#define CLU     8

// Device-global scratch (allocation-free rule: __device__ globals)
__device__ float g_Wpack[G4 * KPAD];   // 5.24 MB packed weights
__device__ float g_bsum[G4];           // b_ih + b_hh, reordered
__device__ float g_hbuf[B_ * H_];      // recurrent h (L2-coherent via cg)
__device__ float g_ybuf[B_ * 2];       // fed-back predicted pos

// ---------------------------------------------------------------------------
// helpers
// ---------------------------------------------------------------------------
__device__ __forceinline__ unsigned long long pk2(float lo, float hi) {
    unsigned long long r;
    asm("mov.b64 %0, {%1, %2};" : "=l"(r) : "f"(lo), "f"(hi));
    return r;
}
__device__ __forceinline__ void upk2(unsigned long long v, float& lo, float& hi) {
    asm("mov.b64 {%0, %1}, %2;" : "=f"(lo), "=f"(hi) : "l"(v));
}
// packed f32x2 FMA: acc = a*b + acc  (2 fp32 lanes per instruction)
#define FMA2(acc, a, b) asm("fma.rn.f32x2 %0, %1, %2, %0;" : "+l"(acc) : "l"(a), "l"(b))

__device__ __forceinline__ void cluster_sync_() {
    asm volatile("barrier.cluster.arrive.aligned;" ::: "memory");
    asm volatile("barrier.cluster.wait.aligned;" ::: "memory");
}

__device__ __forceinline__ float sigf(float v)   { return 1.f / (1.f + __expf(-v)); }
__device__ __forceinline__ float tanhf_(float v) { return 2.f / (1.f + __expf(-2.f * v)) - 1.f; }

// ---------------------------------------------------------------------------
// one-time weight packing: Wpack[rho][k], rho = (rank*4 + gate)*64 + unit
// k<105 -> W_ih[gcol][k]; 105<=k<617 -> W_hh[gcol][k-105]; else 0.
// ---------------------------------------------------------------------------
__global__ void pack_kernel(const float* __restrict__ W_ih,
                            const float* __restrict__ W_hh,
                            const float* __restrict__ b_ih,
                            const float* __restrict__ b_hh) {
    int stride = gridDim.x * blockDim.x;
    for (int idx = blockIdx.x * blockDim.x + threadIdx.x; idx < G4 * KPAD; idx += stride) {
        int rho = idx / KPAD;
        int k   = idx - rho * KPAD;
        int r = rho >> 8;
        int local = rho & 255;
        int q = local >> 6;
        int j = local & 63;
        int gcol = q * H_ + r * 64 + j;
        float v = 0.f;
        if (k < 105)       v = W_ih[gcol * 105 + k];
        else if (k < KTOT) v = W_hh[gcol * H_ + (k - 105)];
        g_Wpack[idx] = v;
        if (k == 0) g_bsum[rho] = b_ih[gcol] + b_hh[gcol];
    }
}

// ---------------------------------------------------------------------------
// persistent recurrent kernel: 16 independent batch groups, 8-CTA clusters
// ---------------------------------------------------------------------------
struct __align__(16) SM {
    float2 inpP[NPAIR][KROW];   // [row-pair][k] : {row2mp, row2mp+1}   79.9 KB
    float  g_s[4][64][33];      // gates [gate][unit][row] (+pad)       33.8 KB
    float  c_s[64][33];         // cell state slice [unit][row] (+pad)   8.4 KB
    float  hm_s[4][H_];         // staged h rows for MLP                 8.2 KB
    float  y1_s[4][64];
    float  y2_s[4][16];
};

__global__ void __launch_bounds__(NTHREADS, 1) __cluster_dims__(CLU, 1, 1)
lstm_kernel(const float* __restrict__ x,  const float* __restrict__ pos,
            const float* __restrict__ h0, const float* __restrict__ c0,
            const float* __restrict__ W1, const float* __restrict__ b1,
            const float* __restrict__ W2, const float* __restrict__ b2,
            const float* __restrict__ W3, const float* __restrict__ b3,
            float* __restrict__ out) {
    extern __shared__ char smraw[];
    SM& sm = *reinterpret_cast<SM*>(smraw);

    const int tid = threadIdx.x;
    const int grp = blockIdx.x >> 3;   // batch group (16)
    const int rnk = blockIdx.x & 7;    // cluster rank = hidden slice
    const int b0  = grp * MB;
    const int q = tid >> 6, j = tid & 63;  // this thread's gate / unit column

    // ---- init state ----
    for (int idx = tid; idx < 64 * MB; idx += NTHREADS) {
        int jj = idx & 63, row = idx >> 6;
        int b = b0 + row, u = rnk * 64 + jj;
        sm.c_s[jj][row] = c0[b * H_ + u];
        __stcg(&g_hbuf[b * H_ + u], h0[b * H_ + u]);
    }
    if (tid < 8) {
        int rr = tid >> 1, o = tid & 1;
        int b = b0 + rnk * 4 + rr;
        __stcg(&g_ybuf[b * 2 + o], pos[b * L_ * 2 + o]);   // pos[:,0,:]
    }
    __threadfence();
    cluster_sync_();

    const float4* wrow = reinterpret_cast<const float4*>(g_Wpack)
                         + (size_t)(rnk * 256 + tid) * (KPAD / 4);
    const float bias = g_bsum[rnk * 256 + tid];

    for (int t = 0; t < L_; t++) {
        // ---- fill input tile: [x_t | y_prev | h_prev] as row-pairs ----
        for (int idx = tid; idx < NPAIR * KP; idx += NTHREADS) {
            int mp = idx / KP;
            int k  = idx - mp * KP;
            int ba = b0 + 2 * mp;
            float va, vb;
            if (k < KOBS) {
                va = x[(ba * L_ + t) * KOBS + k];
                vb = x[((ba + 1) * L_ + t) * KOBS + k];
            } else if (k < 105) {
                va = __ldcg(&g_ybuf[ba * 2 + (k - KOBS)]);
                vb = __ldcg(&g_ybuf[(ba + 1) * 2 + (k - KOBS)]);
            } else if (k < KTOT) {
                va = __ldcg(&g_hbuf[ba * H_ + (k - 105)]);
                vb = __ldcg(&g_hbuf[(ba + 1) * H_ + (k - 105)]);
            } else { va = 0.f; vb = 0.f; }
            sm.inpP[mp][k] = make_float2(va, vb);
        }
        cluster_sync_();   // input tile ready; also fences prior h/y reads vs new writes

        // ---- gate GEMM: this thread = one gate column, 16 row-pairs, K=620 ----
        unsigned long long acc[NPAIR];
        {
            unsigned long long bb = pk2(bias, bias);
            #pragma unroll
            for (int mp = 0; mp < NPAIR; mp++) acc[mp] = bb;
        }
        float4 wv = __ldg(&wrow[0]);
        #pragma unroll 1
        for (int kb = 0; kb < KP / 4; kb++) {
            float4 wn = __ldg(&wrow[kb + 1]);   // prefetch (in-bounds: KPAD padding)
            unsigned long long w0 = pk2(wv.x, wv.x);
            unsigned long long w1 = pk2(wv.y, wv.y);
            unsigned long long w2 = pk2(wv.z, wv.z);
            unsigned long long w3 = pk2(wv.w, wv.w);
            #pragma unroll
            for (int mp = 0; mp < NPAIR; mp++) {
                const ulonglong2* p =
                    reinterpret_cast<const ulonglong2*>(&sm.inpP[mp][kb * 4]);
                ulonglong2 p01 = p[0];
                ulonglong2 p23 = p[1];
                FMA2(acc[mp], w0, p01.x);
                FMA2(acc[mp], w1, p01.y);
                FMA2(acc[mp], w2, p23.x);
                FMA2(acc[mp], w3, p23.y);
            }
            wv = wn;
        }
        #pragma unroll
        for (int mp = 0; mp < NPAIR; mp++) {
            float lo, hi;
            upk2(acc[mp], lo, hi);
            sm.g_s[q][j][2 * mp]     = lo;
            sm.g_s[q][j][2 * mp + 1] = hi;
        }
        __syncthreads();

        // ---- LSTM elementwise update (own 64-unit slice, 32 rows) ----
        {
            int j2 = tid & 63;
            int rb = (tid >> 6) * 8;
            #pragma unroll
            for (int rr = 0; rr < 8; rr++) {
                int row = rb + rr;
                float gi = sm.g_s[0][j2][row];
                float gf = sm.g_s[1][j2][row];
                float gg = sm.g_s[2][j2][row];
                float go = sm.g_s[3][j2][row];
                float c  = sm.c_s[j2][row];
                c = sigf(gf) * c + sigf(gi) * tanhf_(gg);
                float h = sigf(go) * tanhf_(c);
                sm.c_s[j2][row] = c;
                __stcg(&g_hbuf[(b0 + row) * H_ + rnk * 64 + j2], h);
            }
        }
        __threadfence();
        cluster_sync_();   // full h for this group visible

        // ---- MLP head for my 4 rows: 512 -> 64 -> 16 -> 2 (ReLU) ----
        {
            int rbase = b0 + rnk * 4;
            for (int idx = tid; idx < 4 * H_; idx += NTHREADS) {
                int rr = idx >> 9, k = idx & 511;
                sm.hm_s[rr][k] = __ldcg(&g_hbuf[(rbase + rr) * H_ + k]);
            }
            __syncthreads();
            {
                int o = tid & 63, rr = tid >> 6;
                const float4* w1r = reinterpret_cast<const float4*>(W1 + o * H_);
                const float4* hr  = reinterpret_cast<const float4*>(sm.hm_s[rr]);
                float a0 = 0.f, a1 = 0.f, a2 = 0.f, a3 = 0.f;
                #pragma unroll 8
                for (int kk = 0; kk < H_ / 4; kk++) {
                    float4 w  = __ldg(&w1r[kk]);
                    float4 h4 = hr[kk];
                    a0 += w.x * h4.x; a1 += w.y * h4.y;
                    a2 += w.z * h4.z; a3 += w.w * h4.w;
                }
                float v = a0 + a1 + a2 + a3 + __ldg(&b1[o]);
                sm.y1_s[rr][o] = fmaxf(v, 0.f);
            }
            __syncthreads();
            if (tid < 64) {
                int o = tid & 15, rr = tid >> 4;
                float a = __ldg(&b2[o]);
                #pragma unroll
                for (int kk = 0; kk < 64; kk++)
                    a += __ldg(&W2[o * 64 + kk]) * sm.y1_s[rr][kk];
                sm.y2_s[rr][o] = fmaxf(a, 0.f);
            }
            __syncthreads();
            if (tid < 8) {
                int o = tid & 1, rr = tid >> 1;
                float a = __ldg(&b3[o]);
                #pragma unroll
                for (int kk = 0; kk < 16; kk++)
                    a += __ldg(&W3[o * 16 + kk]) * sm.y2_s[rr][kk];
                a = fmaxf(a, 0.f);
                int b = rbase + rr;
                out[(b * L_ + t) * 2 + o] = a;       // predicted_pos[b, t, o]
                __stcg(&g_ybuf[b * 2 + o], a);       // feedback
            }
        }
        __threadfence();
        cluster_sync_();   // y ready for next step's fill
    }

    // ---- final h, c outputs ----
    for (int idx = tid; idx < 64 * MB; idx += NTHREADS) {
        int jj = idx & 63, row = idx >> 6;
        int b = b0 + row, u = rnk * 64 + jj;
        out[B_ * L_ * 2 + b * H_ + u]            = __ldcg(&g_hbuf[b * H_ + u]);
        out[B_ * L_ * 2 + B_ * H_ + b * H_ + u]  = sm.c_s[jj][row];
    }
}

// ---------------------------------------------------------------------------
extern "C" void kernel_launch(void* const* d_in, const int* in_sizes, int n_in,
                              void* d_out, int out_size) {
    const float* x    = (const float*)d_in[0];
    const float* pos  = (const float*)d_in[1];
    const float* h0   = (const float*)d_in[2];
    const float* c0   = (const float*)d_in[3];
    const float* W_ih = (const float*)d_in[4];
    const float* W_hh = (const float*)d_in[5];
    const float* b_ih = (const float*)d_in[6];
    const float* b_hh = (const float*)d_in[7];
    const float* W1   = (const float*)d_in[8];
    const float* b1   = (const float*)d_in[9];
    const float* W2   = (const float*)d_in[10];
    const float* b2   = (const float*)d_in[11];
    const float* W3   = (const float*)d_in[12];
    const float* b3   = (const float*)d_in[13];
    float* out = (float*)d_out;

    pack_kernel<<<256, 256>>>(W_ih, W_hh, b_ih, b_hh);

    cudaFuncSetAttribute(lstm_kernel,
                         cudaFuncAttributeMaxDynamicSharedMemorySize,
                         (int)sizeof(SM));
    lstm_kernel<<<NCTAS, NTHREADS, sizeof(SM)>>>(x, pos, h0, c0,
                                                 W1, b1, W2, b2, W3, b3, out);
}